// round 6
// baseline (speedup 1.0000x reference)
#include <cuda_runtime.h>
#include <cstdint>
#include <math.h>

#define TPB 256
#define CH 30
#define MAXG 4096

__device__ float g_partials[MAXG];
__device__ int   g_count;            // zero-init; reset by last block each launch

__global__ void __launch_bounds__(TPB, 3)
yolo_mlp(const float* __restrict__ predicts,
         const float* __restrict__ targets,
         int n_cells, float* __restrict__ out)
{
    __shared__ float red[TPB];
    __shared__ bool  is_last;

    const int tid  = threadIdx.x;
    const int cell = blockIdx.x * TPB + tid;

    float loss = 0.0f;

    if (cell < n_cells) {
        const long long base = (long long)cell * CH;
        const float2* p2 = reinterpret_cast<const float2*>(predicts + base);
        const float2* t2 = reinterpret_cast<const float2*>(targets + base);

        // ---- Front-batched unconditional loads (high MLP) ----
        float p[CH];
        float tb[6];          // t[0..5] (box + conf; 5 used)
        float tc[20];         // t[10..29] (classes)
#pragma unroll
        for (int j = 0; j < 15; j++) {        // predicts: all 30
            float2 a = __ldg(p2 + j);
            p[2 * j] = a.x; p[2 * j + 1] = a.y;
        }
#pragma unroll
        for (int j = 0; j < 3; j++) {         // targets box/conf
            float2 b = __ldg(t2 + j);
            tb[2 * j] = b.x; tb[2 * j + 1] = b.y;
        }
#pragma unroll
        for (int j = 0; j < 10; j++) {        // targets classes t[10..29]
            float2 b = __ldg(t2 + 5 + j);
            tc[2 * j] = b.x; tc[2 * j + 1] = b.y;
        }

        // ---- Branchless compute ----
        // IoU is translation-invariant: the (+grid)*ratio offset is common to
        // pred and target boxes, so it cancels in mins/maxes and areas.
        const float ratio = 1.0f / 7.0f;

        float tcx = tb[0] * ratio, tcy = tb[1] * ratio;
        float tw = tb[2], th = tb[3];
        float tx1 = tcx - tw * 0.5f, ty1 = tcy - th * 0.5f;
        float tx2 = tcx + tw * 0.5f, ty2 = tcy + th * 0.5f;
        float areaT = (tx2 - tx1) * (ty2 - ty1);

        auto iou_with = [&](const float* b) -> float {
            float bcx = b[0] * ratio, bcy = b[1] * ratio;
            float bw = b[2], bh = b[3];
            float x1 = bcx - bw * 0.5f, y1 = bcy - bh * 0.5f;
            float x2 = bcx + bw * 0.5f, y2 = bcy + bh * 0.5f;
            float iw = fmaxf(fminf(x2, tx2) - fmaxf(x1, tx1), 0.0f);
            float ih = fmaxf(fminf(y2, ty2) - fmaxf(y1, ty1), 0.0f);
            float inter = iw * ih;
            float area = (x2 - x1) * (y2 - y1);
            return inter / (area + areaT - inter);
        };

        float iou1 = iou_with(p);
        float iou2 = iou_with(p + 5);
        bool resp = iou1 > iou2;
        float pcx = resp ? p[0] : p[5];
        float pcy = resp ? p[1] : p[6];
        float pcw = resp ? p[2] : p[7];
        float pch = resp ? p[3] : p[8];
        float pcc = resp ? p[4] : p[9];
        float iouS = resp ? iou1 : iou2;

        float dx = pcx - tb[0];
        float dy = pcy - tb[1];
        float sw = sqrtf(fmaxf(pcw, 1e-6f)) - sqrtf(fmaxf(tb[2], 1e-6f));
        float sh = sqrtf(fmaxf(pch, 1e-6f)) - sqrtf(fmaxf(tb[3], 1e-6f));
        float coord = 5.0f * (dx * dx + dy * dy + sw * sw + sh * sh);

        float dc = pcc - iouS;
        float conf = dc * dc;

        float cls = 0.0f;
#pragma unroll
        for (int k = 0; k < 20; k++) {
            float d = p[10 + k] - tc[k];
            cls += d * d;
        }

        float obj_loss   = coord + conf + cls;
        float noobj_loss = 0.5f * (p[4] * p[4] + p[9] * p[9]);

        loss = (tb[4] > 0.0f) ? obj_loss : noobj_loss;
    }

    // deterministic block tree reduction
    red[tid] = loss;
    __syncthreads();
#pragma unroll
    for (int s = TPB / 2; s >= 32; s >>= 1) {
        if (tid < s) red[tid] += red[tid + s];
        __syncthreads();
    }
    if (tid < 32) {
        float v = red[tid];
#pragma unroll
        for (int off = 16; off > 0; off >>= 1)
            v += __shfl_down_sync(0xFFFFFFFFu, v, off);
        if (tid == 0) {
            g_partials[blockIdx.x] = v;
            __threadfence();
            int old = atomicAdd(&g_count, 1);
            is_last = (old == gridDim.x - 1);
        }
    }
    __syncthreads();

    // last block reduces all partials in a fixed order (deterministic)
    if (is_last) {
        const int nb = gridDim.x;
        float v = 0.0f;
        for (int i = tid; i < nb; i += TPB)
            v += g_partials[i];
        red[tid] = v;
        __syncthreads();
#pragma unroll
        for (int s = TPB / 2; s >= 32; s >>= 1) {
            if (tid < s) red[tid] += red[tid + s];
            __syncthreads();
        }
        if (tid < 32) {
            float w = red[tid];
#pragma unroll
            for (int off = 16; off > 0; off >>= 1)
                w += __shfl_down_sync(0xFFFFFFFFu, w, off);
            if (tid == 0) {
                out[0] = w;
                g_count = 0;            // reset for next graph replay
            }
        }
    }
}

extern "C" void kernel_launch(void* const* d_in, const int* in_sizes, int n_in,
                              void* d_out, int out_size)
{
    const float* predicts = (const float*)d_in[0];
    const float* targets  = (const float*)d_in[1];
    float* out = (float*)d_out;

    int n_cells = in_sizes[0] / CH;                 // 401408
    int blocks = (n_cells + TPB - 1) / TPB;         // 1568
    if (blocks > MAXG) blocks = MAXG;               // not hit for this shape

    yolo_mlp<<<blocks, TPB>>>(predicts, targets, n_cells, out);
}

// round 11
// speedup vs baseline: 1.1967x; 1.1967x over previous
#include <cuda_runtime.h>
#include <cstdint>
#include <math.h>

#define TPB 128           // threads per block == cells per block
#define CH 30             // channels per cell
#define MAX_BLOCKS 8192

__device__ float g_partials[MAX_BLOCKS];

// Per-cell YOLO loss (reads this thread's cell from shared memory).
// IoU is translation-invariant: the (+grid)*ratio offsets cancel, so no
// grid-coordinate math is needed at all.
__device__ __forceinline__ float cell_loss(const float* __restrict__ p,
                                           const float* __restrict__ t)
{
    const float ratio = 1.0f / 7.0f;
    const float tconf = t[4];

    if (!(tconf > 0.0f)) {
        // no-object cell: lambda_noobj * (conf1^2 + conf2^2)
        float c1 = p[4], c2 = p[9];
        return 0.5f * (c1 * c1 + c2 * c2);
    }

    float tcx = t[0] * ratio, tcy = t[1] * ratio;
    float tw = t[2], th = t[3];
    float tx1 = tcx - tw * 0.5f, ty1 = tcy - th * 0.5f;
    float tx2 = tcx + tw * 0.5f, ty2 = tcy + th * 0.5f;
    float areaT = (tx2 - tx1) * (ty2 - ty1);

    auto iou_with = [&](const float* b) -> float {
        float bcx = b[0] * ratio, bcy = b[1] * ratio;
        float bw = b[2], bh = b[3];
        float x1 = bcx - bw * 0.5f, y1 = bcy - bh * 0.5f;
        float x2 = bcx + bw * 0.5f, y2 = bcy + bh * 0.5f;
        float iw = fmaxf(fminf(x2, tx2) - fmaxf(x1, tx1), 0.0f);
        float ih = fmaxf(fminf(y2, ty2) - fmaxf(y1, ty1), 0.0f);
        float inter = iw * ih;
        float area = (x2 - x1) * (y2 - y1);
        return inter / (area + areaT - inter);
    };

    float iou1 = iou_with(p);
    float iou2 = iou_with(p + 5);
    bool resp = iou1 > iou2;
    const float* pc = resp ? p : (p + 5);
    float iouS = resp ? iou1 : iou2;

    float dx = pc[0] - t[0];
    float dy = pc[1] - t[1];
    float sw = sqrtf(fmaxf(pc[2], 1e-6f)) - sqrtf(fmaxf(t[2], 1e-6f));
    float sh = sqrtf(fmaxf(pc[3], 1e-6f)) - sqrtf(fmaxf(t[3], 1e-6f));
    float coord = 5.0f * (dx * dx + dy * dy + sw * sw + sh * sh);

    float dc = pc[4] - iouS;
    float conf = dc * dc;

    float cls = 0.0f;
#pragma unroll
    for (int k = 10; k < 30; k++) {
        float d = p[k] - t[k];
        cls += d * d;
    }
    return coord + conf + cls;
}

__global__ void __launch_bounds__(TPB)
yolo_loss_main(const float* __restrict__ predicts,
               const float* __restrict__ targets,
               int n_cells)
{
    __shared__ float sp[TPB * CH];   // 15360 B
    __shared__ float st[TPB * CH];   // 15360 B

    const int tid = threadIdx.x;
    const int tile_cell0 = blockIdx.x * TPB;
    const int cells_here = min(TPB, n_cells - tile_cell0);
    const long long float_base = (long long)tile_cell0 * CH;

    // Cooperative coalesced load of the tile into shared memory.
    if (cells_here == TPB) {
        const float4* p4 = reinterpret_cast<const float4*>(predicts + float_base);
        const float4* t4 = reinterpret_cast<const float4*>(targets + float_base);
        float4* sp4 = reinterpret_cast<float4*>(sp);
        float4* st4 = reinterpret_cast<float4*>(st);
#pragma unroll
        for (int i = 0; i < 7; i++) {          // 7 full rounds of 128 float4
            int idx = i * TPB + tid;
            sp4[idx] = p4[idx];
            st4[idx] = t4[idx];
        }
        if (tid < 64) {                        // 960 - 7*128 = 64
            int idx = 7 * TPB + tid;
            sp4[idx] = p4[idx];
            st4[idx] = t4[idx];
        }
    } else {
        const int n_floats = cells_here * CH;
        for (int i = tid; i < n_floats; i += TPB) {
            sp[i] = predicts[float_base + i];
            st[i] = targets[float_base + i];
        }
    }
    __syncthreads();

    float loss = 0.0f;
    if (tid < cells_here)
        loss = cell_loss(sp + tid * CH, st + tid * CH);
    __syncthreads();

    // Deterministic block tree reduction (reuse sp as scratch).
    sp[tid] = loss;
    __syncthreads();
#pragma unroll
    for (int s = TPB / 2; s >= 32; s >>= 1) {
        if (tid < s) sp[tid] += sp[tid + s];
        __syncthreads();
    }
    if (tid < 32) {
        float v = sp[tid];
#pragma unroll
        for (int off = 16; off > 0; off >>= 1)
            v += __shfl_down_sync(0xFFFFFFFFu, v, off);
        if (tid == 0) g_partials[blockIdx.x] = v;
    }
}

// Minimal final reduction: single 256-thread block, ~12 independent strided
// loads per thread (L2-hot), fixed order -> deterministic.
__global__ void __launch_bounds__(256)
yolo_loss_final(int n_partials, float* __restrict__ out)
{
    __shared__ float red[256];
    const int tid = threadIdx.x;
    float v = 0.0f;
#pragma unroll 4
    for (int i = tid; i < n_partials; i += 256)
        v += g_partials[i];
    red[tid] = v;
    __syncthreads();
#pragma unroll
    for (int s = 128; s >= 32; s >>= 1) {
        if (tid < s) red[tid] += red[tid + s];
        __syncthreads();
    }
    if (tid < 32) {
        float w = red[tid];
#pragma unroll
        for (int off = 16; off > 0; off >>= 1)
            w += __shfl_down_sync(0xFFFFFFFFu, w, off);
        if (tid == 0) out[0] = w;
    }
}

extern "C" void kernel_launch(void* const* d_in, const int* in_sizes, int n_in,
                              void* d_out, int out_size)
{
    const float* predicts = (const float*)d_in[0];
    const float* targets  = (const float*)d_in[1];
    float* out = (float*)d_out;

    int n_cells = in_sizes[0] / CH;            // 8192*7*7 = 401408
    int blocks = (n_cells + TPB - 1) / TPB;    // 3136
    if (blocks > MAX_BLOCKS) blocks = MAX_BLOCKS;

    yolo_loss_main<<<blocks, TPB>>>(predicts, targets, n_cells);
    yolo_loss_final<<<1, 256>>>(blocks, out);
}